// round 14
// baseline (speedup 1.0000x reference)
#include <cuda_runtime.h>
#include <cuda_bf16.h>
#include <cstdint>
#include <cstddef>

// ---------------- problem constants ----------------
#define T 4096
#define D 1024
#define F 768
#define E 64
#define TOPK 8
#define P (T*TOPK)          // 32768

#define GM 128              // M tile
#define GN 128              // N tile
#define KC 32               // K chunk (fp32 elems) = 128B rows
#define NT_MAX (P/GM + E)   // 320

#define NC1 (D/KC)          // 32
#define NC2 (F/KC)          // 24

#define TB 16384            // tile bytes: 128 rows x 128B
#define STAGE1 (3*TB)       // A, G, U
#define STAGE2 (2*TB)       // A, B
#define SMEM_G1 (3*STAGE1)  // 147456
#define SMEM_G2 (3*STAGE2)  // 98304

// ---------------- device scratch ----------------
__device__ float d_logits[T*E];
__device__ int   d_topk_ids[P];
__device__ float d_topk_w[P];
__device__ int   d_counts[E];
__device__ int   d_pair_token[P];
__device__ int   d_pair_slot[P];
__device__ float d_pair_w[P];
__device__ int   d_tile_expert[NT_MAX];
__device__ int   d_tile_rowstart[NT_MAX];
__device__ int   d_tile_rows[NT_MAX];
__device__ int   d_num_tiles;

__device__ __align__(16) float d_h[(size_t)P*F];
__device__ __align__(16) float d_slots[(size_t)P*D];

// ---------------- helpers ----------------
__device__ __forceinline__ uint32_t smem_u32(const void* p) {
    uint32_t a;
    asm("{ .reg .u64 t; cvta.to.shared.u64 t, %1; cvt.u32.u64 %0, t; }" : "=r"(a) : "l"(p));
    return a;
}

#define CP16(dst, src) asm volatile("cp.async.cg.shared.global [%0], [%1], 16;" :: "r"(dst), "l"(src))
#define CP_COMMIT() asm volatile("cp.async.commit_group;" ::: "memory")
#define CP_WAIT0()  asm volatile("cp.async.wait_group 0;" ::: "memory")
#define CP_WAIT1()  asm volatile("cp.async.wait_group 1;" ::: "memory")

// m16n8k8 tf32 MMA
__device__ __forceinline__ void mma_tf32(float* d, const uint32_t* a, uint32_t b0, uint32_t b1) {
    asm volatile("mma.sync.aligned.m16n8k8.row.col.f32.tf32.tf32.f32 "
        "{%0,%1,%2,%3}, {%4,%5,%6,%7}, {%8,%9}, {%0,%1,%2,%3};"
        : "+f"(d[0]), "+f"(d[1]), "+f"(d[2]), "+f"(d[3])
        : "r"(a[0]), "r"(a[1]), "r"(a[2]), "r"(a[3]), "r"(b0), "r"(b1));
}

// load adjacent fp32 pair (r, c),(r, c+1) from swizzled tile, round both to tf32.
// Used with the k-permutation: instruction slots {lc, lc+4} hold logical k {2lc, 2lc+1}.
__device__ __forceinline__ void ldtf2(uint32_t tile, int r, int c, uint32_t& t0, uint32_t& t1) {
    int ch = c >> 2;
    uint32_t addr = tile + r*128 + (uint32_t)((ch ^ ((r & 3) << 1)) << 4) + (uint32_t)((c & 3) << 2);
    float vx, vy;
    asm volatile("ld.shared.v2.f32 {%0,%1}, [%2];" : "=f"(vx), "=f"(vy) : "r"(addr));
    asm("cvt.rna.tf32.f32 %0, %1;" : "=r"(t0) : "f"(vx));
    asm("cvt.rna.tf32.f32 %0, %1;" : "=r"(t1) : "f"(vy));
}

// ---------------- routing kernels ----------------
__global__ void gate_gemm_kernel(const float* __restrict__ x,
                                 const float* __restrict__ gw) {
    __shared__ float As[32][65];
    __shared__ float Bs[32][65];
    int tid = threadIdx.x;
    if (blockIdx.x == 0 && tid < E) d_counts[tid] = 0;
    int ty = tid / 16, tx = tid % 16;
    int m0 = blockIdx.x * 64;
    float acc[4][4];
    #pragma unroll
    for (int i = 0; i < 4; i++) {
        #pragma unroll
        for (int j = 0; j < 4; j++) acc[i][j] = 0.f;
    }
    for (int k0 = 0; k0 < D; k0 += 32) {
        #pragma unroll
        for (int i = 0; i < 8; i++) {
            int l = tid + i*256; int m = l >> 5, k = l & 31;
            As[k][m] = x[(size_t)(m0+m)*D + k0 + k];
        }
        #pragma unroll
        for (int i = 0; i < 8; i++) {
            int l = tid + i*256; int n = l >> 5, k = l & 31;
            Bs[k][n] = gw[(size_t)n*D + k0 + k];
        }
        __syncthreads();
        #pragma unroll
        for (int k = 0; k < 32; k++) {
            float a[4], b[4];
            #pragma unroll
            for (int i = 0; i < 4; i++) a[i] = As[k][ty*4+i];
            #pragma unroll
            for (int j = 0; j < 4; j++) b[j] = Bs[k][tx*4+j];
            #pragma unroll
            for (int i = 0; i < 4; i++) {
                #pragma unroll
                for (int j = 0; j < 4; j++) acc[i][j] += a[i]*b[j];
            }
        }
        __syncthreads();
    }
    #pragma unroll
    for (int i = 0; i < 4; i++) {
        int m = m0 + ty*4 + i;
        #pragma unroll
        for (int j = 0; j < 4; j++)
            d_logits[(size_t)m*E + tx*4 + j] = acc[i][j];
    }
}

__global__ void topk_kernel() {
    int gwarp = (blockIdx.x * blockDim.x + threadIdx.x) >> 5;
    int lane = threadIdx.x & 31;
    if (gwarp >= T) return;
    float l0 = d_logits[(size_t)gwarp*E + lane];
    float l1 = d_logits[(size_t)gwarp*E + 32 + lane];
    float mx = fmaxf(l0, l1);
    #pragma unroll
    for (int o=16;o;o>>=1) mx = fmaxf(mx, __shfl_xor_sync(0xffffffffu, mx, o));
    float e0 = __expf(l0 - mx), e1 = __expf(l1 - mx);
    float s = e0 + e1;
    #pragma unroll
    for (int o=16;o;o>>=1) s += __shfl_xor_sync(0xffffffffu, s, o);
    float v0 = e0 / s, v1 = e1 / s;
    float tw[8]; int ti[8]; float wsum = 0.f;
    #pragma unroll
    for (int it = 0; it < 8; it++) {
        float best; int bidx;
        if (v0 >= v1) { best = v0; bidx = lane; }
        else          { best = v1; bidx = lane + 32; }
        #pragma unroll
        for (int o=16;o;o>>=1) {
            float ov = __shfl_xor_sync(0xffffffffu, best, o);
            int   oi = __shfl_xor_sync(0xffffffffu, bidx, o);
            if (ov > best || (ov == best && oi < bidx)) { best = ov; bidx = oi; }
        }
        tw[it] = best; ti[it] = bidx;
        if (bidx == lane)      v0 = -1.f;
        if (bidx == lane + 32) v1 = -1.f;
        wsum += best;
    }
    if (lane == 0) {
        float inv = 1.f / (wsum + 1e-20f);
        #pragma unroll
        for (int i = 0; i < 8; i++) {
            d_topk_ids[gwarp*8 + i] = ti[i];
            d_topk_w[gwarp*8 + i]  = tw[i] * inv;
            atomicAdd(&d_counts[ti[i]], 1);
        }
    }
}

__global__ void scanscatter_kernel() {
    __shared__ int cur_s[E];
    int tid = threadIdx.x;
    if (tid == 0) {
        int off = 0, nt = 0;
        for (int e = 0; e < E; e++) {
            cur_s[e] = off;
            int c = d_counts[e];
            for (int r = 0; r < c; r += GM) {
                d_tile_expert[nt]   = e;
                d_tile_rowstart[nt] = off + r;
                d_tile_rows[nt]     = (c - r < GM) ? (c - r) : GM;
                nt++;
            }
            off += c;
        }
        d_num_tiles = nt;
    }
    __syncthreads();
    for (int idx = tid; idx < P; idx += blockDim.x) {
        int e = d_topk_ids[idx];
        int pos = atomicAdd(&cur_s[e], 1);
        d_pair_token[pos] = idx >> 3;
        d_pair_slot[pos]  = idx;
        d_pair_w[pos]     = d_topk_w[idx];
    }
}

// ---------------- G1: h = silu(x@Wg^T)*(x@Wu^T), TF32 + v2 loads ----------------
__global__ __launch_bounds__(256, 1)
void g1_mma_kernel(const float* __restrict__ x,
                   const float* __restrict__ w_gate,
                   const float* __restrict__ w_up) {
    extern __shared__ char smem[];
    __shared__ int rowtok_s[GM];
    int tile = blockIdx.y;
    if (tile >= d_num_tiles) return;
    int e     = d_tile_expert[tile];
    int row0  = d_tile_rowstart[tile];
    int nrows = d_tile_rows[tile];
    int n0    = blockIdx.x * GN;
    int tid = threadIdx.x;
    int lane = tid & 31, wid = tid >> 5;
    int wm = wid >> 2, wn = wid & 3;   // 2x4 warps, 64x32 tiles

    if (tid < GM) rowtok_s[tid] = d_pair_token[row0 + (tid < nrows ? tid : 0)];
    __syncthreads();

    uint32_t sb = smem_u32(smem);
    const float* Wg = w_gate + (size_t)e * (F*D);
    const float* Wu = w_up   + (size_t)e * (F*D);

    float accG[4][4][4], accU[4][4][4];
    #pragma unroll
    for (int i = 0; i < 4; i++)
        #pragma unroll
        for (int j = 0; j < 4; j++)
            #pragma unroll
            for (int q = 0; q < 4; q++) { accG[i][j][q] = 0.f; accU[i][j][q] = 0.f; }

    auto load_stage = [&](int cidx) {
        uint32_t stage = sb + (cidx % 3) * STAGE1;
        int koff = cidx * KC;
        #pragma unroll
        for (int it = 0; it < 12; it++) {
            int tl = it >> 2;
            int rem = tid + (it & 3) * 256;
            int r = rem >> 3, ch = rem & 7;
            uint32_t dst = stage + tl*TB + r*128 + (uint32_t)((ch ^ ((r & 3) << 1)) << 4);
            const float* src;
            if (tl == 0)      src = x  + (size_t)rowtok_s[r]*D + koff + ch*4;
            else if (tl == 1) src = Wg + (size_t)(n0 + r)*D   + koff + ch*4;
            else              src = Wu + (size_t)(n0 + r)*D   + koff + ch*4;
            CP16(dst, src);
        }
        CP_COMMIT();
    };

    load_stage(0);
    load_stage(1);

    const int lr = lane >> 2;       // row within 8-group
    const int lc = lane & 3;

    #pragma unroll 1
    for (int c = 0; c < NC1; c++) {
        if (c + 1 < NC1) CP_WAIT1(); else CP_WAIT0();
        __syncthreads();
        if (c + 2 < NC1) load_stage(c + 2);
        uint32_t base = sb + (c % 3) * STAGE1;
        #pragma unroll
        for (int s = 0; s < 4; s++) {           // 4 k8 steps per 32-K chunk
            int cA = s*8 + 2*lc;                // k-permuted: slots {lc, lc+4} = logical {2lc, 2lc+1}
            uint32_t a[4][4];
            #pragma unroll
            for (int i = 0; i < 4; i++) {
                int rr = wm*64 + i*16 + lr;
                ldtf2(base, rr,   cA, a[i][0], a[i][2]);
                ldtf2(base, rr+8, cA, a[i][1], a[i][3]);
            }
            uint32_t bg[4][2], bu[4][2];
            #pragma unroll
            for (int j = 0; j < 4; j++) {
                int br = wn*32 + j*8 + lr;
                ldtf2(base + TB,   br, cA, bg[j][0], bg[j][1]);
                ldtf2(base + 2*TB, br, cA, bu[j][0], bu[j][1]);
            }
            #pragma unroll
            for (int j = 0; j < 4; j++)
                #pragma unroll
                for (int i = 0; i < 4; i++) mma_tf32(accG[i][j], a[i], bg[j][0], bg[j][1]);
            #pragma unroll
            for (int j = 0; j < 4; j++)
                #pragma unroll
                for (int i = 0; i < 4; i++) mma_tf32(accU[i][j], a[i], bu[j][0], bu[j][1]);
        }
        __syncthreads();
    }

    // epilogue: silu(g)*u -> fp32 h
    int rbase = wm*64, cb = wn*32;
    #pragma unroll
    for (int i = 0; i < 4; i++) {
        #pragma unroll
        for (int j = 0; j < 4; j++) {
            #pragma unroll
            for (int half = 0; half < 2; half++) {
                int r = rbase + i*16 + lr + half*8;
                if (r < nrows) {
                    int col = n0 + cb + j*8 + lc*2;
                    float g0 = accG[i][j][half*2],   g1 = accG[i][j][half*2+1];
                    float u0 = accU[i][j][half*2],   u1 = accU[i][j][half*2+1];
                    float2 h;
                    h.x = g0 / (1.f + __expf(-g0)) * u0;
                    h.y = g1 / (1.f + __expf(-g1)) * u1;
                    *(float2*)&d_h[(size_t)(row0 + r)*F + col] = h;
                }
            }
        }
    }
}

// ---------------- G2: slots = pair_w * (h @ Wd^T), TF32 + v2 loads ----------------
__global__ __launch_bounds__(256, 1)
void g2_mma_kernel(const float* __restrict__ w_down) {
    extern __shared__ char smem[];
    int tile = blockIdx.y;
    if (tile >= d_num_tiles) return;
    int e     = d_tile_expert[tile];
    int row0  = d_tile_rowstart[tile];
    int nrows = d_tile_rows[tile];
    int n0    = blockIdx.x * GN;
    int tid = threadIdx.x;
    int lane = tid & 31, wid = tid >> 5;
    int wm = wid >> 2, wn = wid & 3;

    uint32_t sb = smem_u32(smem);
    const float* Wd = w_down + (size_t)e * (D*F);

    float acc[4][4][4];
    #pragma unroll
    for (int i = 0; i < 4; i++)
        #pragma unroll
        for (int j = 0; j < 4; j++)
            #pragma unroll
            for (int q = 0; q < 4; q++) acc[i][j][q] = 0.f;

    auto load_stage = [&](int cidx) {
        uint32_t stage = sb + (cidx % 3) * STAGE2;
        int koff = cidx * KC;
        #pragma unroll
        for (int it = 0; it < 8; it++) {
            int tl = it >> 2;
            int rem = tid + (it & 3) * 256;
            int r = rem >> 3, ch = rem & 7;
            uint32_t dst = stage + tl*TB + r*128 + (uint32_t)((ch ^ ((r & 3) << 1)) << 4);
            const float* src;
            if (tl == 0) src = d_h + (size_t)(row0 + (r < nrows ? r : 0))*F + koff + ch*4;
            else         src = Wd  + (size_t)(n0 + r)*F + koff + ch*4;
            CP16(dst, src);
        }
        CP_COMMIT();
    };

    load_stage(0);
    load_stage(1);

    const int lr = lane >> 2;
    const int lc = lane & 3;

    #pragma unroll 1
    for (int c = 0; c < NC2; c++) {
        if (c + 1 < NC2) CP_WAIT1(); else CP_WAIT0();
        __syncthreads();
        if (c + 2 < NC2) load_stage(c + 2);
        uint32_t base = sb + (c % 3) * STAGE2;
        #pragma unroll
        for (int s = 0; s < 4; s++) {
            int cA = s*8 + 2*lc;                // k-permuted
            uint32_t a[4][4];
            #pragma unroll
            for (int i = 0; i < 4; i++) {
                int rr = wm*64 + i*16 + lr;
                ldtf2(base, rr,   cA, a[i][0], a[i][2]);
                ldtf2(base, rr+8, cA, a[i][1], a[i][3]);
            }
            uint32_t b[4][2];
            #pragma unroll
            for (int j = 0; j < 4; j++) {
                int br = wn*32 + j*8 + lr;
                ldtf2(base + TB, br, cA, b[j][0], b[j][1]);
            }
            #pragma unroll
            for (int j = 0; j < 4; j++)
                #pragma unroll
                for (int i = 0; i < 4; i++) mma_tf32(acc[i][j], a[i], b[j][0], b[j][1]);
        }
        __syncthreads();
    }

    int rbase = wm*64, cb = wn*32;
    #pragma unroll
    for (int i = 0; i < 4; i++) {
        #pragma unroll
        for (int j = 0; j < 4; j++) {
            #pragma unroll
            for (int half = 0; half < 2; half++) {
                int r = rbase + i*16 + lr + half*8;
                if (r < nrows) {
                    int col = n0 + cb + j*8 + lc*2;
                    int slot = d_pair_slot[row0 + r];
                    float w  = d_pair_w[row0 + r];
                    float2 v;
                    v.x = acc[i][j][half*2]   * w;
                    v.y = acc[i][j][half*2+1] * w;
                    *(float2*)&d_slots[(size_t)slot*D + col] = v;
                }
            }
        }
    }
}

// y[t,d] = sum_k slots[t*8+k, d]
__global__ void combine_kernel(float* __restrict__ y) {
    int idx = blockIdx.x * blockDim.x + threadIdx.x;
    if (idx >= T*D) return;
    int t = idx / D, dd = idx % D;
    float s = 0.f;
    #pragma unroll
    for (int k = 0; k < 8; k++)
        s += d_slots[((size_t)t*8 + k)*D + dd];
    y[idx] = s;
}

// ---------------- launch ----------------
extern "C" void kernel_launch(void* const* d_in, const int* in_sizes, int n_in,
                              void* d_out, int out_size) {
    const float* x  = (const float*)d_in[0];
    const float* gw = (const float*)d_in[1];
    const float* wg = (const float*)d_in[2];
    const float* wu = (const float*)d_in[3];
    const float* wd = (const float*)d_in[4];
    float* y = (float*)d_out;

    cudaFuncSetAttribute(g1_mma_kernel, cudaFuncAttributeMaxDynamicSharedMemorySize, SMEM_G1);
    cudaFuncSetAttribute(g2_mma_kernel, cudaFuncAttributeMaxDynamicSharedMemorySize, SMEM_G2);

    gate_gemm_kernel<<<T/64, 256>>>(x, gw);
    topk_kernel<<<T/4, 128>>>();
    scanscatter_kernel<<<1, 256>>>();
    g1_mma_kernel<<<dim3(F/GN, NT_MAX), 256, SMEM_G1>>>(x, wg, wu);   // launch 4 (profiled)
    g2_mma_kernel<<<dim3(D/GN, NT_MAX), 256, SMEM_G2>>>(wd);
    combine_kernel<<<(T*D)/256, 256>>>(y);
}

// round 15
// speedup vs baseline: 1.0163x; 1.0163x over previous
#include <cuda_runtime.h>
#include <cuda_bf16.h>
#include <cstdint>
#include <cstddef>

// ---------------- problem constants ----------------
#define T 4096
#define D 1024
#define F 768
#define E 64
#define TOPK 8
#define P (T*TOPK)          // 32768

#define GM 128              // M tile
#define GN 128              // N tile
#define KC 32               // K chunk (fp32 elems) = 128B rows
#define NT_MAX (P/GM + E)   // 320

#define NC1 (D/KC)          // 32
#define NC2 (F/KC)          // 24

#define TB 16384            // tile bytes: 128 rows x 128B
#define STAGE1 (3*TB)       // A, G, U
#define STAGE2 (2*TB)       // A, B
#define SMEM_G1 (3*STAGE1)  // 147456
#define SMEM_G2 (3*STAGE2)  // 98304

// ---------------- device scratch ----------------
__device__ float d_logits[T*E];
__device__ int   d_topk_ids[P];
__device__ float d_topk_w[P];
__device__ int   d_counts[E];
__device__ int   d_pair_token[P];
__device__ int   d_pair_slot[P];
__device__ float d_pair_w[P];
__device__ int   d_tile_expert[NT_MAX];
__device__ int   d_tile_rowstart[NT_MAX];
__device__ int   d_tile_rows[NT_MAX];
__device__ int   d_num_tiles;

__device__ __align__(16) float d_h[(size_t)P*F];
__device__ __align__(16) float d_slots[(size_t)P*D];

// ---------------- helpers ----------------
__device__ __forceinline__ uint32_t smem_u32(const void* p) {
    uint32_t a;
    asm("{ .reg .u64 t; cvta.to.shared.u64 t, %1; cvt.u32.u64 %0, t; }" : "=r"(a) : "l"(p));
    return a;
}

#define CP16(dst, src) asm volatile("cp.async.cg.shared.global [%0], [%1], 16;" :: "r"(dst), "l"(src))
#define CP_COMMIT() asm volatile("cp.async.commit_group;" ::: "memory")
#define CP_WAIT0()  asm volatile("cp.async.wait_group 0;" ::: "memory")
#define CP_WAIT1()  asm volatile("cp.async.wait_group 1;" ::: "memory")

// m16n8k8 tf32 MMA
__device__ __forceinline__ void mma_tf32(float* d, const uint32_t* a, uint32_t b0, uint32_t b1) {
    asm volatile("mma.sync.aligned.m16n8k8.row.col.f32.tf32.tf32.f32 "
        "{%0,%1,%2,%3}, {%4,%5,%6,%7}, {%8,%9}, {%0,%1,%2,%3};"
        : "+f"(d[0]), "+f"(d[1]), "+f"(d[2]), "+f"(d[3])
        : "r"(a[0]), "r"(a[1]), "r"(a[2]), "r"(a[3]), "r"(b0), "r"(b1));
}

// load one fp32 from swizzled tile, round to tf32
__device__ __forceinline__ uint32_t ldtf(uint32_t tile, int r, int c) {
    int ch = c >> 2;
    uint32_t addr = tile + r*128 + (uint32_t)((ch ^ ((r & 3) << 1)) << 4) + (uint32_t)((c & 3) << 2);
    float v;
    asm volatile("ld.shared.f32 %0, [%1];" : "=f"(v) : "r"(addr));
    uint32_t t;
    asm("cvt.rna.tf32.f32 %0, %1;" : "=r"(t) : "f"(v));
    return t;
}

// ---------------- routing kernels ----------------
__global__ void gate_gemm_kernel(const float* __restrict__ x,
                                 const float* __restrict__ gw) {
    __shared__ float As[32][65];
    __shared__ float Bs[32][65];
    int tid = threadIdx.x;
    if (blockIdx.x == 0 && tid < E) d_counts[tid] = 0;
    int ty = tid / 16, tx = tid % 16;
    int m0 = blockIdx.x * 64;
    float acc[4][4];
    #pragma unroll
    for (int i = 0; i < 4; i++) {
        #pragma unroll
        for (int j = 0; j < 4; j++) acc[i][j] = 0.f;
    }
    for (int k0 = 0; k0 < D; k0 += 32) {
        #pragma unroll
        for (int i = 0; i < 8; i++) {
            int l = tid + i*256; int m = l >> 5, k = l & 31;
            As[k][m] = x[(size_t)(m0+m)*D + k0 + k];
        }
        #pragma unroll
        for (int i = 0; i < 8; i++) {
            int l = tid + i*256; int n = l >> 5, k = l & 31;
            Bs[k][n] = gw[(size_t)n*D + k0 + k];
        }
        __syncthreads();
        #pragma unroll
        for (int k = 0; k < 32; k++) {
            float a[4], b[4];
            #pragma unroll
            for (int i = 0; i < 4; i++) a[i] = As[k][ty*4+i];
            #pragma unroll
            for (int j = 0; j < 4; j++) b[j] = Bs[k][tx*4+j];
            #pragma unroll
            for (int i = 0; i < 4; i++) {
                #pragma unroll
                for (int j = 0; j < 4; j++) acc[i][j] += a[i]*b[j];
            }
        }
        __syncthreads();
    }
    #pragma unroll
    for (int i = 0; i < 4; i++) {
        int m = m0 + ty*4 + i;
        #pragma unroll
        for (int j = 0; j < 4; j++)
            d_logits[(size_t)m*E + tx*4 + j] = acc[i][j];
    }
}

__global__ void topk_kernel() {
    int gwarp = (blockIdx.x * blockDim.x + threadIdx.x) >> 5;
    int lane = threadIdx.x & 31;
    if (gwarp >= T) return;
    float l0 = d_logits[(size_t)gwarp*E + lane];
    float l1 = d_logits[(size_t)gwarp*E + 32 + lane];
    float mx = fmaxf(l0, l1);
    #pragma unroll
    for (int o=16;o;o>>=1) mx = fmaxf(mx, __shfl_xor_sync(0xffffffffu, mx, o));
    float e0 = __expf(l0 - mx), e1 = __expf(l1 - mx);
    float s = e0 + e1;
    #pragma unroll
    for (int o=16;o;o>>=1) s += __shfl_xor_sync(0xffffffffu, s, o);
    float v0 = e0 / s, v1 = e1 / s;
    float tw[8]; int ti[8]; float wsum = 0.f;
    #pragma unroll
    for (int it = 0; it < 8; it++) {
        float best; int bidx;
        if (v0 >= v1) { best = v0; bidx = lane; }
        else          { best = v1; bidx = lane + 32; }
        #pragma unroll
        for (int o=16;o;o>>=1) {
            float ov = __shfl_xor_sync(0xffffffffu, best, o);
            int   oi = __shfl_xor_sync(0xffffffffu, bidx, o);
            if (ov > best || (ov == best && oi < bidx)) { best = ov; bidx = oi; }
        }
        tw[it] = best; ti[it] = bidx;
        if (bidx == lane)      v0 = -1.f;
        if (bidx == lane + 32) v1 = -1.f;
        wsum += best;
    }
    if (lane == 0) {
        float inv = 1.f / (wsum + 1e-20f);
        #pragma unroll
        for (int i = 0; i < 8; i++) {
            d_topk_ids[gwarp*8 + i] = ti[i];
            d_topk_w[gwarp*8 + i]  = tw[i] * inv;
            atomicAdd(&d_counts[ti[i]], 1);
        }
    }
}

__global__ void scanscatter_kernel() {
    __shared__ int cur_s[E];
    int tid = threadIdx.x;
    if (tid == 0) {
        int off = 0, nt = 0;
        for (int e = 0; e < E; e++) {
            cur_s[e] = off;
            int c = d_counts[e];
            for (int r = 0; r < c; r += GM) {
                d_tile_expert[nt]   = e;
                d_tile_rowstart[nt] = off + r;
                d_tile_rows[nt]     = (c - r < GM) ? (c - r) : GM;
                nt++;
            }
            off += c;
        }
        d_num_tiles = nt;
    }
    __syncthreads();
    for (int idx = tid; idx < P; idx += blockDim.x) {
        int e = d_topk_ids[idx];
        int pos = atomicAdd(&cur_s[e], 1);
        d_pair_token[pos] = idx >> 3;
        d_pair_slot[pos]  = idx;
        d_pair_w[pos]     = d_topk_w[idx];
    }
}

// ---------------- G1: h = silu(x@Wg^T)*(x@Wu^T), TF32 + fragment pipeline ----------------
__global__ __launch_bounds__(256, 1)
void g1_mma_kernel(const float* __restrict__ x,
                   const float* __restrict__ w_gate,
                   const float* __restrict__ w_up) {
    extern __shared__ char smem[];
    __shared__ int rowtok_s[GM];
    int tile = blockIdx.y;
    if (tile >= d_num_tiles) return;
    int e     = d_tile_expert[tile];
    int row0  = d_tile_rowstart[tile];
    int nrows = d_tile_rows[tile];
    int n0    = blockIdx.x * GN;
    int tid = threadIdx.x;
    int lane = tid & 31, wid = tid >> 5;
    int wm = wid >> 2, wn = wid & 3;   // 2x4 warps, 64x32 tiles

    if (tid < GM) rowtok_s[tid] = d_pair_token[row0 + (tid < nrows ? tid : 0)];
    __syncthreads();

    uint32_t sb = smem_u32(smem);
    const float* Wg = w_gate + (size_t)e * (F*D);
    const float* Wu = w_up   + (size_t)e * (F*D);

    float accG[4][4][4], accU[4][4][4];
    #pragma unroll
    for (int i = 0; i < 4; i++)
        #pragma unroll
        for (int j = 0; j < 4; j++)
            #pragma unroll
            for (int q = 0; q < 4; q++) { accG[i][j][q] = 0.f; accU[i][j][q] = 0.f; }

    auto load_stage = [&](int cidx) {
        uint32_t stage = sb + (cidx % 3) * STAGE1;
        int koff = cidx * KC;
        #pragma unroll
        for (int it = 0; it < 12; it++) {
            int tl = it >> 2;
            int rem = tid + (it & 3) * 256;
            int r = rem >> 3, ch = rem & 7;
            uint32_t dst = stage + tl*TB + r*128 + (uint32_t)((ch ^ ((r & 3) << 1)) << 4);
            const float* src;
            if (tl == 0)      src = x  + (size_t)rowtok_s[r]*D + koff + ch*4;
            else if (tl == 1) src = Wg + (size_t)(n0 + r)*D   + koff + ch*4;
            else              src = Wu + (size_t)(n0 + r)*D   + koff + ch*4;
            CP16(dst, src);
        }
        CP_COMMIT();
    };

    load_stage(0);
    load_stage(1);

    const int lr = lane >> 2;       // row within 8-group
    const int lc = lane & 3;        // k index within 4

    // double-buffered fragments across k8 steps
    uint32_t aF[2][16], bgF[2][8], buF[2][8];

    auto load_frags = [&](uint32_t base, int s, int buf) {
        int cA = s*8 + lc;
        #pragma unroll
        for (int i = 0; i < 4; i++) {
            int rr = wm*64 + i*16 + lr;
            aF[buf][i*4+0] = ldtf(base, rr,   cA);
            aF[buf][i*4+1] = ldtf(base, rr+8, cA);
            aF[buf][i*4+2] = ldtf(base, rr,   cA+4);
            aF[buf][i*4+3] = ldtf(base, rr+8, cA+4);
        }
        #pragma unroll
        for (int j = 0; j < 4; j++) {
            int br = wn*32 + j*8 + lr;
            bgF[buf][j*2+0] = ldtf(base + TB,   br, cA);
            bgF[buf][j*2+1] = ldtf(base + TB,   br, cA+4);
            buF[buf][j*2+0] = ldtf(base + 2*TB, br, cA);
            buF[buf][j*2+1] = ldtf(base + 2*TB, br, cA+4);
        }
    };

    #pragma unroll 1
    for (int c = 0; c < NC1; c++) {
        if (c + 1 < NC1) CP_WAIT1(); else CP_WAIT0();
        __syncthreads();
        if (c + 2 < NC1) load_stage(c + 2);
        uint32_t base = sb + (c % 3) * STAGE1;
        load_frags(base, 0, 0);
        #pragma unroll
        for (int s = 0; s < 4; s++) {
            int cur = s & 1, nxt = cur ^ 1;
            if (s < 3) load_frags(base, s + 1, nxt);   // prefetch next step's frags
            #pragma unroll
            for (int j = 0; j < 4; j++)
                #pragma unroll
                for (int i = 0; i < 4; i++)
                    mma_tf32(accG[i][j], &aF[cur][i*4], bgF[cur][j*2], bgF[cur][j*2+1]);
            #pragma unroll
            for (int j = 0; j < 4; j++)
                #pragma unroll
                for (int i = 0; i < 4; i++)
                    mma_tf32(accU[i][j], &aF[cur][i*4], buF[cur][j*2], buF[cur][j*2+1]);
        }
        __syncthreads();
    }

    // epilogue: silu(g)*u -> fp32 h
    int rbase = wm*64, cb = wn*32;
    #pragma unroll
    for (int i = 0; i < 4; i++) {
        #pragma unroll
        for (int j = 0; j < 4; j++) {
            #pragma unroll
            for (int half = 0; half < 2; half++) {
                int r = rbase + i*16 + lr + half*8;
                if (r < nrows) {
                    int col = n0 + cb + j*8 + lc*2;
                    float g0 = accG[i][j][half*2],   g1 = accG[i][j][half*2+1];
                    float u0 = accU[i][j][half*2],   u1 = accU[i][j][half*2+1];
                    float2 h;
                    h.x = g0 / (1.f + __expf(-g0)) * u0;
                    h.y = g1 / (1.f + __expf(-g1)) * u1;
                    *(float2*)&d_h[(size_t)(row0 + r)*F + col] = h;
                }
            }
        }
    }
}

// ---------------- G2: slots = pair_w * (h @ Wd^T), TF32 + fragment pipeline ----------------
__global__ __launch_bounds__(256, 1)
void g2_mma_kernel(const float* __restrict__ w_down) {
    extern __shared__ char smem[];
    int tile = blockIdx.y;
    if (tile >= d_num_tiles) return;
    int e     = d_tile_expert[tile];
    int row0  = d_tile_rowstart[tile];
    int nrows = d_tile_rows[tile];
    int n0    = blockIdx.x * GN;
    int tid = threadIdx.x;
    int lane = tid & 31, wid = tid >> 5;
    int wm = wid >> 2, wn = wid & 3;

    uint32_t sb = smem_u32(smem);
    const float* Wd = w_down + (size_t)e * (D*F);

    float acc[4][4][4];
    #pragma unroll
    for (int i = 0; i < 4; i++)
        #pragma unroll
        for (int j = 0; j < 4; j++)
            #pragma unroll
            for (int q = 0; q < 4; q++) acc[i][j][q] = 0.f;

    auto load_stage = [&](int cidx) {
        uint32_t stage = sb + (cidx % 3) * STAGE2;
        int koff = cidx * KC;
        #pragma unroll
        for (int it = 0; it < 8; it++) {
            int tl = it >> 2;
            int rem = tid + (it & 3) * 256;
            int r = rem >> 3, ch = rem & 7;
            uint32_t dst = stage + tl*TB + r*128 + (uint32_t)((ch ^ ((r & 3) << 1)) << 4);
            const float* src;
            if (tl == 0) src = d_h + (size_t)(row0 + (r < nrows ? r : 0))*F + koff + ch*4;
            else         src = Wd  + (size_t)(n0 + r)*F + koff + ch*4;
            CP16(dst, src);
        }
        CP_COMMIT();
    };

    load_stage(0);
    load_stage(1);

    const int lr = lane >> 2;
    const int lc = lane & 3;

    uint32_t aF[2][16], bF[2][8];

    auto load_frags = [&](uint32_t base, int s, int buf) {
        int cA = s*8 + lc;
        #pragma unroll
        for (int i = 0; i < 4; i++) {
            int rr = wm*64 + i*16 + lr;
            aF[buf][i*4+0] = ldtf(base, rr,   cA);
            aF[buf][i*4+1] = ldtf(base, rr+8, cA);
            aF[buf][i*4+2] = ldtf(base, rr,   cA+4);
            aF[buf][i*4+3] = ldtf(base, rr+8, cA+4);
        }
        #pragma unroll
        for (int j = 0; j < 4; j++) {
            int br = wn*32 + j*8 + lr;
            bF[buf][j*2+0] = ldtf(base + TB, br, cA);
            bF[buf][j*2+1] = ldtf(base + TB, br, cA+4);
        }
    };

    #pragma unroll 1
    for (int c = 0; c < NC2; c++) {
        if (c + 1 < NC2) CP_WAIT1(); else CP_WAIT0();
        __syncthreads();
        if (c + 2 < NC2) load_stage(c + 2);
        uint32_t base = sb + (c % 3) * STAGE2;
        load_frags(base, 0, 0);
        #pragma unroll
        for (int s = 0; s < 4; s++) {
            int cur = s & 1, nxt = cur ^ 1;
            if (s < 3) load_frags(base, s + 1, nxt);
            #pragma unroll
            for (int j = 0; j < 4; j++)
                #pragma unroll
                for (int i = 0; i < 4; i++)
                    mma_tf32(acc[i][j], &aF[cur][i*4], bF[cur][j*2], bF[cur][j*2+1]);
        }
        __syncthreads();
    }

    int rbase = wm*64, cb = wn*32;
    #pragma unroll
    for (int i = 0; i < 4; i++) {
        #pragma unroll
        for (int j = 0; j < 4; j++) {
            #pragma unroll
            for (int half = 0; half < 2; half++) {
                int r = rbase + i*16 + lr + half*8;
                if (r < nrows) {
                    int col = n0 + cb + j*8 + lc*2;
                    int slot = d_pair_slot[row0 + r];
                    float w  = d_pair_w[row0 + r];
                    float2 v;
                    v.x = acc[i][j][half*2]   * w;
                    v.y = acc[i][j][half*2+1] * w;
                    *(float2*)&d_slots[(size_t)slot*D + col] = v;
                }
            }
        }
    }
}

// y[t,d] = sum_k slots[t*8+k, d]
__global__ void combine_kernel(float* __restrict__ y) {
    int idx = blockIdx.x * blockDim.x + threadIdx.x;
    if (idx >= T*D) return;
    int t = idx / D, dd = idx % D;
    float s = 0.f;
    #pragma unroll
    for (int k = 0; k < 8; k++)
        s += d_slots[((size_t)t*8 + k)*D + dd];
    y[idx] = s;
}

// ---------------- launch ----------------
extern "C" void kernel_launch(void* const* d_in, const int* in_sizes, int n_in,
                              void* d_out, int out_size) {
    const float* x  = (const float*)d_in[0];
    const float* gw = (const float*)d_in[1];
    const float* wg = (const float*)d_in[2];
    const float* wu = (const float*)d_in[3];
    const float* wd = (const float*)d_in[4];
    float* y = (float*)d_out;

    cudaFuncSetAttribute(g1_mma_kernel, cudaFuncAttributeMaxDynamicSharedMemorySize, SMEM_G1);
    cudaFuncSetAttribute(g2_mma_kernel, cudaFuncAttributeMaxDynamicSharedMemorySize, SMEM_G2);

    gate_gemm_kernel<<<T/64, 256>>>(x, gw);
    topk_kernel<<<T/4, 128>>>();
    scanscatter_kernel<<<1, 256>>>();
    g1_mma_kernel<<<dim3(F/GN, NT_MAX), 256, SMEM_G1>>>(x, wg, wu);   // launch 4 (profiled)
    g2_mma_kernel<<<dim3(D/GN, NT_MAX), 256, SMEM_G2>>>(wd);
    combine_kernel<<<(T*D)/256, 256>>>(y);
}

// round 17
// speedup vs baseline: 1.0843x; 1.0669x over previous
#include <cuda_runtime.h>
#include <cuda_bf16.h>
#include <cstdint>
#include <cstddef>

// ---------------- problem constants ----------------
#define T 4096
#define D 1024
#define F 768
#define E 64
#define TOPK 8
#define P (T*TOPK)          // 32768

#define GM 128              // M tile
#define GN 128              // N tile
#define KC 32               // K chunk (fp32 elems) = 128B rows
#define NT_MAX (P/GM + E)   // 320

#define NC1 (D/KC)          // 32
#define NC2 (F/KC)          // 24

#define TB 16384            // tile bytes: 128 rows x 128B
#define STAGE1 (3*TB)       // A, G, U
#define STAGE2 (2*TB)       // A, B
#define SMEM_G1 (3*STAGE1)  // 147456
#define SMEM_G2 (3*STAGE2)  // 98304

// ---------------- device scratch ----------------
__device__ float d_logits[T*E];
__device__ int   d_topk_ids[P];
__device__ float d_topk_w[P];
__device__ int   d_counts[E];
__device__ int   d_pair_token[P];
__device__ int   d_pair_slot[P];
__device__ float d_pair_w[P];
__device__ int   d_tile_expert[NT_MAX];
__device__ int   d_tile_rowstart[NT_MAX];
__device__ int   d_tile_rows[NT_MAX];
__device__ int   d_num_tiles;

__device__ __align__(16) float d_h[(size_t)P*F];
__device__ __align__(16) float d_slots[(size_t)P*D];

// ---------------- helpers ----------------
__device__ __forceinline__ uint32_t smem_u32(const void* p) {
    uint32_t a;
    asm("{ .reg .u64 t; cvta.to.shared.u64 t, %1; cvt.u32.u64 %0, t; }" : "=r"(a) : "l"(p));
    return a;
}

#define CP16(dst, src) asm volatile("cp.async.cg.shared.global [%0], [%1], 16;" :: "r"(dst), "l"(src))
#define CP_COMMIT() asm volatile("cp.async.commit_group;" ::: "memory")
#define CP_WAIT0()  asm volatile("cp.async.wait_group 0;" ::: "memory")
#define CP_WAIT1()  asm volatile("cp.async.wait_group 1;" ::: "memory")

// m16n8k8 tf32 MMA
__device__ __forceinline__ void mma_tf32(float* d, const uint32_t* a, uint32_t b0, uint32_t b1) {
    asm volatile("mma.sync.aligned.m16n8k8.row.col.f32.tf32.tf32.f32 "
        "{%0,%1,%2,%3}, {%4,%5,%6,%7}, {%8,%9}, {%0,%1,%2,%3};"
        : "+f"(d[0]), "+f"(d[1]), "+f"(d[2]), "+f"(d[3])
        : "r"(a[0]), "r"(a[1]), "r"(a[2]), "r"(a[3]), "r"(b0), "r"(b1));
}

// load one fp32 from swizzled tile, round to tf32.
// swizzle: 16B-chunk index XOR (row & 7) -> fragment loads (ch const per instr,
// rows spanning 8) hit all 32 banks.
__device__ __forceinline__ uint32_t ldtf(uint32_t tile, int r, int c) {
    int ch = c >> 2;
    uint32_t addr = tile + r*128 + (uint32_t)((ch ^ (r & 7)) << 4) + (uint32_t)((c & 3) << 2);
    float v;
    asm volatile("ld.shared.f32 %0, [%1];" : "=f"(v) : "r"(addr));
    uint32_t t;
    asm("cvt.rna.tf32.f32 %0, %1;" : "=r"(t) : "f"(v));
    return t;
}

// ---------------- routing kernels ----------------
__global__ void gate_gemm_kernel(const float* __restrict__ x,
                                 const float* __restrict__ gw) {
    __shared__ float As[32][65];
    __shared__ float Bs[32][65];
    int tid = threadIdx.x;
    if (blockIdx.x == 0 && tid < E) d_counts[tid] = 0;
    int ty = tid / 16, tx = tid % 16;
    int m0 = blockIdx.x * 64;
    float acc[4][4];
    #pragma unroll
    for (int i = 0; i < 4; i++) {
        #pragma unroll
        for (int j = 0; j < 4; j++) acc[i][j] = 0.f;
    }
    for (int k0 = 0; k0 < D; k0 += 32) {
        #pragma unroll
        for (int i = 0; i < 8; i++) {
            int l = tid + i*256; int m = l >> 5, k = l & 31;
            As[k][m] = x[(size_t)(m0+m)*D + k0 + k];
        }
        #pragma unroll
        for (int i = 0; i < 8; i++) {
            int l = tid + i*256; int n = l >> 5, k = l & 31;
            Bs[k][n] = gw[(size_t)n*D + k0 + k];
        }
        __syncthreads();
        #pragma unroll
        for (int k = 0; k < 32; k++) {
            float a[4], b[4];
            #pragma unroll
            for (int i = 0; i < 4; i++) a[i] = As[k][ty*4+i];
            #pragma unroll
            for (int j = 0; j < 4; j++) b[j] = Bs[k][tx*4+j];
            #pragma unroll
            for (int i = 0; i < 4; i++) {
                #pragma unroll
                for (int j = 0; j < 4; j++) acc[i][j] += a[i]*b[j];
            }
        }
        __syncthreads();
    }
    #pragma unroll
    for (int i = 0; i < 4; i++) {
        int m = m0 + ty*4 + i;
        #pragma unroll
        for (int j = 0; j < 4; j++)
            d_logits[(size_t)m*E + tx*4 + j] = acc[i][j];
    }
}

__global__ void topk_kernel() {
    int gwarp = (blockIdx.x * blockDim.x + threadIdx.x) >> 5;
    int lane = threadIdx.x & 31;
    if (gwarp >= T) return;
    float l0 = d_logits[(size_t)gwarp*E + lane];
    float l1 = d_logits[(size_t)gwarp*E + 32 + lane];
    float mx = fmaxf(l0, l1);
    #pragma unroll
    for (int o=16;o;o>>=1) mx = fmaxf(mx, __shfl_xor_sync(0xffffffffu, mx, o));
    float e0 = __expf(l0 - mx), e1 = __expf(l1 - mx);
    float s = e0 + e1;
    #pragma unroll
    for (int o=16;o;o>>=1) s += __shfl_xor_sync(0xffffffffu, s, o);
    float v0 = e0 / s, v1 = e1 / s;
    float tw[8]; int ti[8]; float wsum = 0.f;
    #pragma unroll
    for (int it = 0; it < 8; it++) {
        float best; int bidx;
        if (v0 >= v1) { best = v0; bidx = lane; }
        else          { best = v1; bidx = lane + 32; }
        #pragma unroll
        for (int o=16;o;o>>=1) {
            float ov = __shfl_xor_sync(0xffffffffu, best, o);
            int   oi = __shfl_xor_sync(0xffffffffu, bidx, o);
            if (ov > best || (ov == best && oi < bidx)) { best = ov; bidx = oi; }
        }
        tw[it] = best; ti[it] = bidx;
        if (bidx == lane)      v0 = -1.f;
        if (bidx == lane + 32) v1 = -1.f;
        wsum += best;
    }
    if (lane == 0) {
        float inv = 1.f / (wsum + 1e-20f);
        #pragma unroll
        for (int i = 0; i < 8; i++) {
            d_topk_ids[gwarp*8 + i] = ti[i];
            d_topk_w[gwarp*8 + i]  = tw[i] * inv;
            atomicAdd(&d_counts[ti[i]], 1);
        }
    }
}

__global__ void scanscatter_kernel() {
    __shared__ int cur_s[E];
    int tid = threadIdx.x;
    if (tid == 0) {
        int off = 0, nt = 0;
        for (int e = 0; e < E; e++) {
            cur_s[e] = off;
            int c = d_counts[e];
            for (int r = 0; r < c; r += GM) {
                d_tile_expert[nt]   = e;
                d_tile_rowstart[nt] = off + r;
                d_tile_rows[nt]     = (c - r < GM) ? (c - r) : GM;
                nt++;
            }
            off += c;
        }
        d_num_tiles = nt;
    }
    __syncthreads();
    for (int idx = tid; idx < P; idx += blockDim.x) {
        int e = d_topk_ids[idx];
        int pos = atomicAdd(&cur_s[e], 1);
        d_pair_token[pos] = idx >> 3;
        d_pair_slot[pos]  = idx;
        d_pair_w[pos]     = d_topk_w[idx];
    }
}

// ---------------- G1: h = silu(x@Wg^T)*(x@Wu^T), TF32, conflict-free swizzle ----------------
__global__ __launch_bounds__(256, 1)
void g1_mma_kernel(const float* __restrict__ x,
                   const float* __restrict__ w_gate,
                   const float* __restrict__ w_up) {
    extern __shared__ char smem[];
    __shared__ int rowtok_s[GM];
    int tile = blockIdx.y;
    if (tile >= d_num_tiles) return;
    int e     = d_tile_expert[tile];
    int row0  = d_tile_rowstart[tile];
    int nrows = d_tile_rows[tile];
    int n0    = blockIdx.x * GN;
    int tid = threadIdx.x;
    int lane = tid & 31, wid = tid >> 5;
    int wm = wid >> 2, wn = wid & 3;   // 2x4 warps, 64x32 tiles

    if (tid < GM) rowtok_s[tid] = d_pair_token[row0 + (tid < nrows ? tid : 0)];
    __syncthreads();

    uint32_t sb = smem_u32(smem);
    const float* Wg = w_gate + (size_t)e * (F*D);
    const float* Wu = w_up   + (size_t)e * (F*D);

    float accG[4][4][4], accU[4][4][4];
    #pragma unroll
    for (int i = 0; i < 4; i++)
        #pragma unroll
        for (int j = 0; j < 4; j++)
            #pragma unroll
            for (int q = 0; q < 4; q++) { accG[i][j][q] = 0.f; accU[i][j][q] = 0.f; }

    auto load_stage = [&](int cidx) {
        uint32_t stage = sb + (cidx % 3) * STAGE1;
        int koff = cidx * KC;
        #pragma unroll
        for (int it = 0; it < 12; it++) {
            int tl = it >> 2;
            int rem = tid + (it & 3) * 256;
            int r = rem >> 3, ch = rem & 7;
            uint32_t dst = stage + tl*TB + r*128 + (uint32_t)((ch ^ (r & 7)) << 4);
            const float* src;
            if (tl == 0)      src = x  + (size_t)rowtok_s[r]*D + koff + ch*4;
            else if (tl == 1) src = Wg + (size_t)(n0 + r)*D   + koff + ch*4;
            else              src = Wu + (size_t)(n0 + r)*D   + koff + ch*4;
            CP16(dst, src);
        }
        CP_COMMIT();
    };

    load_stage(0);
    load_stage(1);

    const int lr = lane >> 2;       // row within 8-group
    const int lc = lane & 3;        // k index within 4

    // double-buffered fragments across k8 steps
    uint32_t aF[2][16], bgF[2][8], buF[2][8];

    auto load_frags = [&](uint32_t base, int s, int buf) {
        int cA = s*8 + lc;
        #pragma unroll
        for (int i = 0; i < 4; i++) {
            int rr = wm*64 + i*16 + lr;
            aF[buf][i*4+0] = ldtf(base, rr,   cA);
            aF[buf][i*4+1] = ldtf(base, rr+8, cA);
            aF[buf][i*4+2] = ldtf(base, rr,   cA+4);
            aF[buf][i*4+3] = ldtf(base, rr+8, cA+4);
        }
        #pragma unroll
        for (int j = 0; j < 4; j++) {
            int br = wn*32 + j*8 + lr;
            bgF[buf][j*2+0] = ldtf(base + TB,   br, cA);
            bgF[buf][j*2+1] = ldtf(base + TB,   br, cA+4);
            buF[buf][j*2+0] = ldtf(base + 2*TB, br, cA);
            buF[buf][j*2+1] = ldtf(base + 2*TB, br, cA+4);
        }
    };

    #pragma unroll 1
    for (int c = 0; c < NC1; c++) {
        if (c + 1 < NC1) CP_WAIT1(); else CP_WAIT0();
        __syncthreads();
        if (c + 2 < NC1) load_stage(c + 2);
        uint32_t base = sb + (c % 3) * STAGE1;
        load_frags(base, 0, 0);
        #pragma unroll
        for (int s = 0; s < 4; s++) {
            int cur = s & 1, nxt = cur ^ 1;
            if (s < 3) load_frags(base, s + 1, nxt);   // prefetch next step's frags
            #pragma unroll
            for (int j = 0; j < 4; j++)
                #pragma unroll
                for (int i = 0; i < 4; i++)
                    mma_tf32(accG[i][j], &aF[cur][i*4], bgF[cur][j*2], bgF[cur][j*2+1]);
            #pragma unroll
            for (int j = 0; j < 4; j++)
                #pragma unroll
                for (int i = 0; i < 4; i++)
                    mma_tf32(accU[i][j], &aF[cur][i*4], buF[cur][j*2], buF[cur][j*2+1]);
        }
        __syncthreads();
    }

    // epilogue: silu(g)*u -> fp32 h
    int rbase = wm*64, cb = wn*32;
    #pragma unroll
    for (int i = 0; i < 4; i++) {
        #pragma unroll
        for (int j = 0; j < 4; j++) {
            #pragma unroll
            for (int half = 0; half < 2; half++) {
                int r = rbase + i*16 + lr + half*8;
                if (r < nrows) {
                    int col = n0 + cb + j*8 + lc*2;
                    float g0 = accG[i][j][half*2],   g1 = accG[i][j][half*2+1];
                    float u0 = accU[i][j][half*2],   u1 = accU[i][j][half*2+1];
                    float2 h;
                    h.x = g0 / (1.f + __expf(-g0)) * u0;
                    h.y = g1 / (1.f + __expf(-g1)) * u1;
                    *(float2*)&d_h[(size_t)(row0 + r)*F + col] = h;
                }
            }
        }
    }
}

// ---------------- G2: slots = pair_w * (h @ Wd^T), TF32, conflict-free swizzle ----------------
__global__ __launch_bounds__(256, 1)
void g2_mma_kernel(const float* __restrict__ w_down) {
    extern __shared__ char smem[];
    int tile = blockIdx.y;
    if (tile >= d_num_tiles) return;
    int e     = d_tile_expert[tile];
    int row0  = d_tile_rowstart[tile];
    int nrows = d_tile_rows[tile];
    int n0    = blockIdx.x * GN;
    int tid = threadIdx.x;
    int lane = tid & 31, wid = tid >> 5;
    int wm = wid >> 2, wn = wid & 3;

    uint32_t sb = smem_u32(smem);
    const float* Wd = w_down + (size_t)e * (D*F);

    float acc[4][4][4];
    #pragma unroll
    for (int i = 0; i < 4; i++)
        #pragma unroll
        for (int j = 0; j < 4; j++)
            #pragma unroll
            for (int q = 0; q < 4; q++) acc[i][j][q] = 0.f;

    auto load_stage = [&](int cidx) {
        uint32_t stage = sb + (cidx % 3) * STAGE2;
        int koff = cidx * KC;
        #pragma unroll
        for (int it = 0; it < 8; it++) {
            int tl = it >> 2;
            int rem = tid + (it & 3) * 256;
            int r = rem >> 3, ch = rem & 7;
            uint32_t dst = stage + tl*TB + r*128 + (uint32_t)((ch ^ (r & 7)) << 4);
            const float* src;
            if (tl == 0) src = d_h + (size_t)(row0 + (r < nrows ? r : 0))*F + koff + ch*4;
            else         src = Wd  + (size_t)(n0 + r)*F + koff + ch*4;
            CP16(dst, src);
        }
        CP_COMMIT();
    };

    load_stage(0);
    load_stage(1);

    const int lr = lane >> 2;
    const int lc = lane & 3;

    uint32_t aF[2][16], bF[2][8];

    auto load_frags = [&](uint32_t base, int s, int buf) {
        int cA = s*8 + lc;
        #pragma unroll
        for (int i = 0; i < 4; i++) {
            int rr = wm*64 + i*16 + lr;
            aF[buf][i*4+0] = ldtf(base, rr,   cA);
            aF[buf][i*4+1] = ldtf(base, rr+8, cA);
            aF[buf][i*4+2] = ldtf(base, rr,   cA+4);
            aF[buf][i*4+3] = ldtf(base, rr+8, cA+4);
        }
        #pragma unroll
        for (int j = 0; j < 4; j++) {
            int br = wn*32 + j*8 + lr;
            bF[buf][j*2+0] = ldtf(base + TB, br, cA);
            bF[buf][j*2+1] = ldtf(base + TB, br, cA+4);
        }
    };

    #pragma unroll 1
    for (int c = 0; c < NC2; c++) {
        if (c + 1 < NC2) CP_WAIT1(); else CP_WAIT0();
        __syncthreads();
        if (c + 2 < NC2) load_stage(c + 2);
        uint32_t base = sb + (c % 3) * STAGE2;
        load_frags(base, 0, 0);
        #pragma unroll
        for (int s = 0; s < 4; s++) {
            int cur = s & 1, nxt = cur ^ 1;
            if (s < 3) load_frags(base, s + 1, nxt);
            #pragma unroll
            for (int j = 0; j < 4; j++)
                #pragma unroll
                for (int i = 0; i < 4; i++)
                    mma_tf32(acc[i][j], &aF[cur][i*4], bF[cur][j*2], bF[cur][j*2+1]);
        }
        __syncthreads();
    }

    int rbase = wm*64, cb = wn*32;
    #pragma unroll
    for (int i = 0; i < 4; i++) {
        #pragma unroll
        for (int j = 0; j < 4; j++) {
            #pragma unroll
            for (int half = 0; half < 2; half++) {
                int r = rbase + i*16 + lr + half*8;
                if (r < nrows) {
                    int col = n0 + cb + j*8 + lc*2;
                    int slot = d_pair_slot[row0 + r];
                    float w  = d_pair_w[row0 + r];
                    float2 v;
                    v.x = acc[i][j][half*2]   * w;
                    v.y = acc[i][j][half*2+1] * w;
                    *(float2*)&d_slots[(size_t)slot*D + col] = v;
                }
            }
        }
    }
}

// y[t,d] = sum_k slots[t*8+k, d]
__global__ void combine_kernel(float* __restrict__ y) {
    int idx = blockIdx.x * blockDim.x + threadIdx.x;
    if (idx >= T*D) return;
    int t = idx / D, dd = idx % D;
    float s = 0.f;
    #pragma unroll
    for (int k = 0; k < 8; k++)
        s += d_slots[((size_t)t*8 + k)*D + dd];
    y[idx] = s;
}

// ---------------- launch ----------------
extern "C" void kernel_launch(void* const* d_in, const int* in_sizes, int n_in,
                              void* d_out, int out_size) {
    const float* x  = (const float*)d_in[0];
    const float* gw = (const float*)d_in[1];
    const float* wg = (const float*)d_in[2];
    const float* wu = (const float*)d_in[3];
    const float* wd = (const float*)d_in[4];
    float* y = (float*)d_out;

    cudaFuncSetAttribute(g1_mma_kernel, cudaFuncAttributeMaxDynamicSharedMemorySize, SMEM_G1);
    cudaFuncSetAttribute(g2_mma_kernel, cudaFuncAttributeMaxDynamicSharedMemorySize, SMEM_G2);

    gate_gemm_kernel<<<T/64, 256>>>(x, gw);
    topk_kernel<<<T/4, 128>>>();
    scanscatter_kernel<<<1, 256>>>();
    g1_mma_kernel<<<dim3(F/GN, NT_MAX), 256, SMEM_G1>>>(x, wg, wu);   // launch 4 (profiled)
    g2_mma_kernel<<<dim3(D/GN, NT_MAX), 256, SMEM_G2>>>(wd);
    combine_kernel<<<(T*D)/256, 256>>>(y);
}